// round 14
// baseline (speedup 1.0000x reference)
#include <cuda_runtime.h>

#define BQ 16      // batch
#define NH 32      // heads
#define HD 128     // head dim
#define LL 4096    // seq len
#define CC 1536    // q_lora_rank
#define NW 8       // warps per attention CTA
#define C4 (CC / 4)   // 384 float4 per row
#define RPW 2      // qproj rows per warp

// Scratch for projected q: [B, H, HD] = 256 KB.
__device__ float g_q[BQ * NH * HD];

// ---------------------------------------------------------------------------
// Kernel 1: q = hidden @ w_q^T + b_q      (4096 x 1536 x 16 skinny GEMM)
// 512 CTAs x 128 threads; warp owns 2 rows x all 16 batches (RPW=2 keeps
// regs low enough for >=3 CTAs/SM). Lane indexes the contraction so every
// w_q load is a coalesced 512B LDG.128; 8 independent w-loads per chunk,
// 2x the warps of the RPW=4 version at the same chip-level MLP.
// Triggers programmatic launch completion after its g_q stores so the
// PDL-launched attn kernel can overlap its launch/setup with our tail.
// ---------------------------------------------------------------------------
__global__ void __launch_bounds__(128) qproj_kernel(const float* __restrict__ hidden,
                                                    const float* __restrict__ wq,
                                                    const float* __restrict__ bq) {
    const int warp = threadIdx.x >> 5;
    const int lane = threadIdx.x & 31;
    const int gw   = blockIdx.x * 4 + warp;   // 0..2047
    const int row0 = gw * RPW;

    const float4* w4 = reinterpret_cast<const float4*>(wq);
    const float4* h4 = reinterpret_cast<const float4*>(hidden);

    float acc[RPW][BQ];
    #pragma unroll
    for (int r = 0; r < RPW; r++)
        #pragma unroll
        for (int b = 0; b < BQ; b++) acc[r][b] = 0.0f;

    #pragma unroll
    for (int chunk = 0; chunk < 3; chunk++) {     // 3 chunks x 4 steps = 384 c4
        // Front-batched w preload: 8 independent LDG.128.
        float4 wv[4][RPW];
        #pragma unroll
        for (int st = 0; st < 4; st++)
            #pragma unroll
            for (int r = 0; r < RPW; r++)
                wv[st][r] = w4[(size_t)(row0 + r) * C4 + chunk * 128 + st * 32 + lane];

        #pragma unroll
        for (int st = 0; st < 4; st++) {
            const int c4 = chunk * 128 + st * 32 + lane;
            #pragma unroll
            for (int b = 0; b < BQ; b++) {
                float4 hv = h4[b * C4 + c4];
                #pragma unroll
                for (int r = 0; r < RPW; r++) {
                    acc[r][b] = fmaf(wv[st][r].x, hv.x,
                                fmaf(wv[st][r].y, hv.y,
                                fmaf(wv[st][r].z, hv.z,
                                fmaf(wv[st][r].w, hv.w, acc[r][b]))));
                }
            }
        }
    }

    // Cross-lane reduction: 32 (r,b) outputs per warp via padded smem.
    __shared__ float red[4][32][33];
    #pragma unroll
    for (int r = 0; r < RPW; r++)
        #pragma unroll
        for (int b = 0; b < BQ; b++)
            red[warp][lane][r * BQ + b] = acc[r][b];
    __syncwarp();

    // Lane p sums its (r, b) output over all 32 contraction lanes.
    {
        const int p = lane;
        float s0 = 0.f, s1 = 0.f, s2 = 0.f, s3 = 0.f;
        #pragma unroll
        for (int j = 0; j < 32; j += 4) {
            s0 += red[warp][j + 0][p];
            s1 += red[warp][j + 1][p];
            s2 += red[warp][j + 2][p];
            s3 += red[warp][j + 3][p];
        }
        const int r   = p >> 4;
        const int b   = p & 15;
        const int row = row0 + r;
        g_q[b * (NH * HD) + row] = (s0 + s1) + (s2 + s3) + bq[row];
    }

#if __CUDA_ARCH__ >= 900
    cudaTriggerProgrammaticLaunchCompletion();
#endif
}

// ---------------------------------------------------------------------------
// Kernel 2: fused single-pass attention (R1 structure, frozen: measured at
// the achieved-HBM wall, 307-319 us depending on DVFS state). One CTA per
// (b,h), 512 CTAs, 8 warps x 512 l, 40 regs, plain LDG.128, online softmax
// with warp-uniform rare rescale, intra-CTA smem merge, direct output.
// PDL: all setup happens before cudaGridDependencySynchronize(); g_q is
// read only after the sync.
// ---------------------------------------------------------------------------
__global__ void __launch_bounds__(NW * 32) attn_kernel(const float* __restrict__ Kd,
                                                       const float* __restrict__ Vd,
                                                       float* __restrict__ out) {
    const int bh   = blockIdx.x;          // b*NH + h
    const int b    = bh >> 5;
    const int h    = bh & 31;
    const int warp = threadIdx.x >> 5;
    const int lane = threadIdx.x & 31;

    const int S4  = NH * HD / 4;          // float4 stride between l's = 1024
    const int LPW = LL / NW;              // 512 l per warp
    const size_t base4 = (((size_t)b * LL) * NH + h) * (HD / 4);

    const float4* kp = reinterpret_cast<const float4*>(Kd) + base4
                       + (size_t)(warp * LPW) * S4 + lane;
    const float4* vp = reinterpret_cast<const float4*>(Vd) + base4
                       + (size_t)(warp * LPW) * S4 + lane;

#if __CUDA_ARCH__ >= 900
    cudaGridDependencySynchronize();      // wait for qproj's g_q writes
#endif
    const float4 qv = *reinterpret_cast<const float4*>(g_q + (size_t)bh * HD + 4 * lane);

    float m = -1e30f;                     // running max
    float s = 0.0f;                       // running denom
    float ax = 0.f, ay = 0.f, az = 0.f, aw = 0.f;   // running numerator (k slice)

    #pragma unroll 1
    for (int i = 0; i < LPW; i += 4) {
        // Batch the loads up front for MLP (8 outstanding LDG.128 per warp).
        float4 kv[4], vv[4];
        #pragma unroll
        for (int u = 0; u < 4; u++) {
            kv[u] = kp[(size_t)u * S4];
            vv[u] = vp[(size_t)u * S4];
        }
        kp += 4 * S4;
        vp += 4 * S4;

        #pragma unroll
        for (int u = 0; u < 4; u++) {
            float x = kv[u].x * qv.x + kv[u].y * qv.y + kv[u].z * qv.z + kv[u].w * qv.w;
            x += __shfl_xor_sync(0xffffffffu, x, 16);
            x += __shfl_xor_sync(0xffffffffu, x, 8);
            x += __shfl_xor_sync(0xffffffffu, x, 4);
            x += __shfl_xor_sync(0xffffffffu, x, 2);
            x += __shfl_xor_sync(0xffffffffu, x, 1);

            if (x > m) {                  // warp-uniform, rare (~ln(L) times)
                float sc = __expf(m - x);
                s *= sc; ax *= sc; ay *= sc; az *= sc; aw *= sc;
                m = x;
            }
            float p = __expf(x - m);
            s  += p;
            ax += p * vv[u].x;
            ay += p * vv[u].y;
            az += p * vv[u].z;
            aw += p * vv[u].w;
        }
    }

    // Cross-warp merge.
    __shared__ float  sm_m[NW];
    __shared__ float  sm_s[NW];
    __shared__ float4 sm_acc[NW][32];     // [warp][lane] -> k = 4*lane..+3

    if (lane == 0) { sm_m[warp] = m; sm_s[warp] = s; }
    sm_acc[warp][lane] = make_float4(ax, ay, az, aw);
    __syncthreads();

    if (threadIdx.x < HD) {
        const int k = threadIdx.x;
        float M = sm_m[0];
        #pragma unroll
        for (int w = 1; w < NW; w++) M = fmaxf(M, sm_m[w]);
        float denom = 0.0f, num = 0.0f;
        #pragma unroll
        for (int w = 0; w < NW; w++) {
            float e = __expf(sm_m[w] - M);
            denom += e * sm_s[w];
            num   += e * reinterpret_cast<const float*>(&sm_acc[w][0])[k];
        }
        out[(size_t)bh * HD + k] = num / denom;
    }
}

// ---------------------------------------------------------------------------
// Inputs (metadata order): 0 hidden_states_q [B,1536] f32
//                          1 key_states      [B,L,H,HD] f32
//                          2 value_states    [B,L,H,HD] f32
//                          3 w_q             [H*HD,1536] f32
//                          4 b_q             [H*HD] f32
// Output: [B, H*HD] f32
// ---------------------------------------------------------------------------
extern "C" void kernel_launch(void* const* d_in, const int* in_sizes, int n_in,
                              void* d_out, int out_size) {
    (void)in_sizes; (void)n_in; (void)out_size;
    const float* hidden = (const float*)d_in[0];
    const float* Kd     = (const float*)d_in[1];
    const float* Vd     = (const float*)d_in[2];
    const float* wq     = (const float*)d_in[3];
    const float* bq     = (const float*)d_in[4];
    float* out          = (float*)d_out;

    qproj_kernel<<<(NH * HD) / (RPW * 4), 128>>>(hidden, wq, bq);

    // PDL launch: attn overlaps its launch/setup with qproj's tail; the
    // device-side cudaGridDependencySynchronize() enforces the g_q dependency.
    cudaLaunchConfig_t cfg = {};
    cfg.gridDim  = dim3(BQ * NH);
    cfg.blockDim = dim3(NW * 32);
    cfg.stream   = 0;
    cudaLaunchAttribute attr[1];
    attr[0].id = cudaLaunchAttributeProgrammaticStreamSerialization;
    attr[0].val.programmaticStreamSerializationAllowed = 1;
    cfg.attrs    = attr;
    cfg.numAttrs = 1;
    cudaLaunchKernelEx(&cfg, attn_kernel, Kd, Vd, out);
}

// round 16
// speedup vs baseline: 1.0698x; 1.0698x over previous
#include <cuda_runtime.h>

#define BQ 16      // batch
#define NH 32      // heads
#define HD 128     // head dim
#define LL 4096    // seq len
#define CC 1536    // q_lora_rank
#define NW 8       // warps per attention CTA
#define C4 (CC / 4)   // 384 float4 per row
#define RPW 4      // qproj rows per warp

// Scratch for projected q: [B, H, HD] = 256 KB.
__device__ float g_q[BQ * NH * HD];

// ---------------------------------------------------------------------------
// Kernel 1: q = hidden @ w_q^T + b_q      (4096 x 1536 x 16 skinny GEMM)
// 256 CTAs x 128 threads; warp owns 4 rows x all 16 batches. Lane indexes
// the contraction so every w_q load is a coalesced 512B LDG.128; 16
// independent w-loads issued back-to-back per chunk cover DRAM/L2 latency.
// Steady-state (graph replay): w_q 25 MB is L2-resident -> FMA-floor ~6 us.
// Fires programmatic launch completion after its g_q stores (PDL).
// ---------------------------------------------------------------------------
__global__ void __launch_bounds__(128, 2) qproj_kernel(const float* __restrict__ hidden,
                                                       const float* __restrict__ wq,
                                                       const float* __restrict__ bq) {
    const int warp = threadIdx.x >> 5;
    const int lane = threadIdx.x & 31;
    const int gw   = blockIdx.x * 4 + warp;   // 0..1023
    const int row0 = gw * RPW;

    const float4* w4 = reinterpret_cast<const float4*>(wq);
    const float4* h4 = reinterpret_cast<const float4*>(hidden);

    float acc[RPW][BQ];
    #pragma unroll
    for (int r = 0; r < RPW; r++)
        #pragma unroll
        for (int b = 0; b < BQ; b++) acc[r][b] = 0.0f;

    #pragma unroll
    for (int chunk = 0; chunk < 3; chunk++) {     // 3 chunks x 4 steps = 384 c4
        float4 wv[4][RPW];
        #pragma unroll
        for (int st = 0; st < 4; st++)
            #pragma unroll
            for (int r = 0; r < RPW; r++)
                wv[st][r] = w4[(size_t)(row0 + r) * C4 + chunk * 128 + st * 32 + lane];

        #pragma unroll
        for (int st = 0; st < 4; st++) {
            const int c4 = chunk * 128 + st * 32 + lane;
            #pragma unroll
            for (int b = 0; b < BQ; b++) {
                float4 hv = h4[b * C4 + c4];
                #pragma unroll
                for (int r = 0; r < RPW; r++) {
                    acc[r][b] = fmaf(wv[st][r].x, hv.x,
                                fmaf(wv[st][r].y, hv.y,
                                fmaf(wv[st][r].z, hv.z,
                                fmaf(wv[st][r].w, hv.w, acc[r][b]))));
                }
            }
        }
    }

    // Cross-lane reduction: 64 (r,b) outputs per warp via padded smem.
    __shared__ float red[4][32][65];
    #pragma unroll
    for (int r = 0; r < RPW; r++)
        #pragma unroll
        for (int b = 0; b < BQ; b++)
            red[warp][lane][r * BQ + b] = acc[r][b];
    __syncwarp();

    #pragma unroll
    for (int half = 0; half < 2; half++) {
        const int p = lane + half * 32;
        float s0 = 0.f, s1 = 0.f, s2 = 0.f, s3 = 0.f;
        #pragma unroll
        for (int j = 0; j < 32; j += 4) {
            s0 += red[warp][j + 0][p];
            s1 += red[warp][j + 1][p];
            s2 += red[warp][j + 2][p];
            s3 += red[warp][j + 3][p];
        }
        const int r   = p >> 4;
        const int b   = p & 15;
        const int row = row0 + r;
        g_q[b * (NH * HD) + row] = (s0 + s1) + (s2 + s3) + bq[row];
    }

#if __CUDA_ARCH__ >= 900
    cudaTriggerProgrammaticLaunchCompletion();
#endif
}

// ---------------------------------------------------------------------------
// Kernel 2: fused single-pass attention (FROZEN — measured at the achieved
// HBM wall: 302-319 us @ 86-90% DRAM across rounds, variance = DVFS).
// One CTA per (b,h), 512 CTAs all co-resident (single wave), 8 warps x 512 l,
// 40 regs, plain LDG.128 front-batched 8-deep, online softmax with
// warp-uniform rare rescale, intra-CTA smem merge, direct output.
// PDL: pointer setup before cudaGridDependencySynchronize(); g_q read after.
// ---------------------------------------------------------------------------
__global__ void __launch_bounds__(NW * 32) attn_kernel(const float* __restrict__ Kd,
                                                       const float* __restrict__ Vd,
                                                       float* __restrict__ out) {
    const int bh   = blockIdx.x;          // b*NH + h
    const int b    = bh >> 5;
    const int h    = bh & 31;
    const int warp = threadIdx.x >> 5;
    const int lane = threadIdx.x & 31;

    const int S4  = NH * HD / 4;          // float4 stride between l's = 1024
    const int LPW = LL / NW;              // 512 l per warp
    const size_t base4 = (((size_t)b * LL) * NH + h) * (HD / 4);

    const float4* kp = reinterpret_cast<const float4*>(Kd) + base4
                       + (size_t)(warp * LPW) * S4 + lane;
    const float4* vp = reinterpret_cast<const float4*>(Vd) + base4
                       + (size_t)(warp * LPW) * S4 + lane;

#if __CUDA_ARCH__ >= 900
    cudaGridDependencySynchronize();      // qproj's g_q writes visible after this
#endif
    const float4 qv = *reinterpret_cast<const float4*>(g_q + (size_t)bh * HD + 4 * lane);

    float m = -1e30f;                     // running max
    float s = 0.0f;                       // running denom
    float ax = 0.f, ay = 0.f, az = 0.f, aw = 0.f;   // running numerator (k slice)

    #pragma unroll 1
    for (int i = 0; i < LPW; i += 4) {
        // Batch the loads up front for MLP (8 outstanding LDG.128 per warp).
        float4 kv[4], vv[4];
        #pragma unroll
        for (int u = 0; u < 4; u++) {
            kv[u] = kp[(size_t)u * S4];
            vv[u] = vp[(size_t)u * S4];
        }
        kp += 4 * S4;
        vp += 4 * S4;

        #pragma unroll
        for (int u = 0; u < 4; u++) {
            float x = kv[u].x * qv.x + kv[u].y * qv.y + kv[u].z * qv.z + kv[u].w * qv.w;
            x += __shfl_xor_sync(0xffffffffu, x, 16);
            x += __shfl_xor_sync(0xffffffffu, x, 8);
            x += __shfl_xor_sync(0xffffffffu, x, 4);
            x += __shfl_xor_sync(0xffffffffu, x, 2);
            x += __shfl_xor_sync(0xffffffffu, x, 1);

            if (x > m) {                  // warp-uniform, rare (~ln(L) times)
                float sc = __expf(m - x);
                s *= sc; ax *= sc; ay *= sc; az *= sc; aw *= sc;
                m = x;
            }
            float p = __expf(x - m);
            s  += p;
            ax += p * vv[u].x;
            ay += p * vv[u].y;
            az += p * vv[u].z;
            aw += p * vv[u].w;
        }
    }

    // Cross-warp merge.
    __shared__ float  sm_m[NW];
    __shared__ float  sm_s[NW];
    __shared__ float4 sm_acc[NW][32];     // [warp][lane] -> k = 4*lane..+3

    if (lane == 0) { sm_m[warp] = m; sm_s[warp] = s; }
    sm_acc[warp][lane] = make_float4(ax, ay, az, aw);
    __syncthreads();

    if (threadIdx.x < HD) {
        const int k = threadIdx.x;
        float M = sm_m[0];
        #pragma unroll
        for (int w = 1; w < NW; w++) M = fmaxf(M, sm_m[w]);
        float denom = 0.0f, num = 0.0f;
        #pragma unroll
        for (int w = 0; w < NW; w++) {
            float e = __expf(sm_m[w] - M);
            denom += e * sm_s[w];
            num   += e * reinterpret_cast<const float*>(&sm_acc[w][0])[k];
        }
        out[(size_t)bh * HD + k] = num / denom;
    }
}

// ---------------------------------------------------------------------------
// Inputs (metadata order): 0 hidden_states_q [B,1536] f32
//                          1 key_states      [B,L,H,HD] f32
//                          2 value_states    [B,L,H,HD] f32
//                          3 w_q             [H*HD,1536] f32
//                          4 b_q             [H*HD] f32
// Output: [B, H*HD] f32
// ---------------------------------------------------------------------------
extern "C" void kernel_launch(void* const* d_in, const int* in_sizes, int n_in,
                              void* d_out, int out_size) {
    (void)in_sizes; (void)n_in; (void)out_size;
    const float* hidden = (const float*)d_in[0];
    const float* Kd     = (const float*)d_in[1];
    const float* Vd     = (const float*)d_in[2];
    const float* wq     = (const float*)d_in[3];
    const float* bq     = (const float*)d_in[4];
    float* out          = (float*)d_out;

    qproj_kernel<<<(NH * HD) / (RPW * 4), 128>>>(hidden, wq, bq);

    // PDL launch: attn overlaps its launch/setup with qproj's tail; the
    // device-side cudaGridDependencySynchronize() enforces the g_q dependency.
    cudaLaunchConfig_t cfg = {};
    cfg.gridDim  = dim3(BQ * NH);
    cfg.blockDim = dim3(NW * 32);
    cfg.stream   = 0;
    cudaLaunchAttribute attr[1];
    attr[0].id = cudaLaunchAttributeProgrammaticStreamSerialization;
    attr[0].val.programmaticStreamSerializationAllowed = 1;
    cfg.attrs    = attr;
    cfg.numAttrs = 1;
    cudaLaunchKernelEx(&cfg, attn_kernel, Kd, Vd, out);
}